// round 10
// baseline (speedup 1.0000x reference)
#include <cuda_runtime.h>
#include <math.h>

#define BATCH 8
#define NC 80
#define NA 8400
#define NA0 6400
#define NA1 1600
#define NA2 400
#define PRE_TOPK 5000
#define KMAX 100
#define TOTK (NC*KMAX)
#define SCORE_THR 0.01f
#define IOU_THR 0.65f
#define NTH 256
#define CAP 512
#define TSEL 160
#define FSORT 256
#define PFN 128
#define PADKEY 0xFFFFFFFFFFFFFFFFull
#define FULLM 0xFFFFFFFFu
#define QBASE 0x3F800000u
#define VHI 55040u            /* (bits(110.f)-QBASE)>>10 ; u16 band bound */
typedef unsigned long long u64;
typedef unsigned short u16;

// ---------------- scratch ----------------
__device__ float g_qo[BATCH*NA];         // qapprox(obj) surrogate factor
__device__ float g_kept_score[BATCH*TOTK];
__device__ float g_kept_box  [BATCH*TOTK*4];
__device__ int   g_done[BATCH];          // zero-init; self-resetting per replay

// decision-exact IoU>thr; IEEE div only in tiny ambiguity band
__device__ __forceinline__ bool iou_sup(float4 A, float aar, float4 B, float bar){
    float tlx = fmaxf(A.x, B.x), tly = fmaxf(A.y, B.y);
    float brx = fminf(A.z, B.z), bry = fminf(A.w, B.w);
    float ww = fmaxf(brx - tlx, 0.f), hh = fmaxf(bry - tly, 0.f);
    float inter = ww*hh;
    float denom = aar + bar - inter + 1e-6f;
    float d = inter - IOU_THR*denom;
    if (fabsf(d) > 1e-4f*denom) return d > 0.f;
    return __fdiv_rn(inter, denom) > IOU_THR;
}

// monotone cheap approx of 1+e^{-x} (selection surrogate only)
__device__ __forceinline__ float qapprox(float x){
    float t = fminf(fmaxf(-x, -80.f), 80.f);
    int bits = (int)(12102203.0f*t + 1064986316.0f);
    return 1.0f + __int_as_float(bits);
}

__device__ __forceinline__ u16 q2u16(float q){
    unsigned bits = __float_as_uint(q);
    unsigned v = (bits - QBASE) >> 10;
    return (u16)min(v, 65535u);
}

// warp-aggregated append (final phase)
__device__ __forceinline__ void wappend(u64* buf, int* cnt, bool pred, u64 val, int bound){
    unsigned pm = __ballot_sync(FULLM, pred);
    if (!pm) return;
    int lane = (int)(threadIdx.x & 31);
    int ldr  = __ffs(pm) - 1;
    int base = 0;
    if (lane == ldr) base = atomicAdd(cnt, __popc(pm));
    base = __shfl_sync(FULLM, base, ldr);
    if (pred){
        int p = base + __popc(pm & ((1u<<lane)-1u));
        if (p < bound) buf[p] = val;
    }
}

// exact box decode (identical arithmetic to all passing rounds)
__device__ __forceinline__ float4 decode_box(int a, int b,
        const float* __restrict__ bb0, const float* __restrict__ bb1,
        const float* __restrict__ bb2){
    float p0,p1,p2,p3,px,py,st;
    if (a < NA0){ int hw=a; const float* p=bb0+(size_t)b*4*NA0;
        p0=p[hw];p1=p[NA0+hw];p2=p[2*NA0+hw];p3=p[3*NA0+hw];
        px=(float)(hw%80)*8.f; py=(float)(hw/80)*8.f; st=8.f;
    } else if (a < NA0+NA1){ int hw=a-NA0; const float* p=bb1+(size_t)b*4*NA1;
        p0=p[hw];p1=p[NA1+hw];p2=p[2*NA1+hw];p3=p[3*NA1+hw];
        px=(float)(hw%40)*16.f; py=(float)(hw/40)*16.f; st=16.f;
    } else { int hw=a-NA0-NA1; const float* p=bb2+(size_t)b*4*NA2;
        p0=p[hw];p1=p[NA2+hw];p2=p[2*NA2+hw];p3=p[3*NA2+hw];
        px=(float)(hw%20)*32.f; py=(float)(hw/20)*32.f; st=32.f;
    }
    float cx=p0*st+px, cy=p1*st+py, w=expf(p2)*st, h=expf(p3)*st;
    return make_float4(cx-w*0.5f, cy-h*0.5f, cx+w*0.5f, cy+h*0.5f);
}

__device__ __forceinline__ float cls_at(int a, const float* c0, const float* c1, const float* c2){
    if (a < NA0) return c0[a];
    if (a < NA0+NA1) return c1[a-NA0];
    return c2[a-NA0-NA1];
}
__device__ __forceinline__ float obj_at(int a, const float* o0, const float* o1, const float* o2){
    if (a < NA0) return o0[a];
    if (a < NA0+NA1) return o1[a-NA0];
    return o2[a-NA0-NA1];
}

// ---------------- pre-kernel: objectness surrogate ----------------
__global__ void k_obj(const float* __restrict__ obj0, const float* __restrict__ obj1,
                      const float* __restrict__ obj2){
    int idx = blockIdx.x*blockDim.x + threadIdx.x;
    if (idx >= BATCH*NA) return;
    int a = idx % NA, b = idx / NA;
    float ov;
    if (a < NA0) ov = obj0[(size_t)b*NA0 + a];
    else if (a < NA0+NA1) ov = obj1[(size_t)b*NA1 + (a-NA0)];
    else ov = obj2[(size_t)b*NA2 + (a-NA0-NA1)];
    g_qo[idx] = qapprox(ov);
}

// ---------------- the fused kernel ----------------
__global__ __launch_bounds__(NTH, 6) void k_all(
    const float* __restrict__ cls0, const float* __restrict__ bb0, const float* __restrict__ obj0,
    const float* __restrict__ cls1, const float* __restrict__ bb1, const float* __restrict__ obj1,
    const float* __restrict__ cls2, const float* __restrict__ bb2, const float* __restrict__ obj2,
    float* __restrict__ out){

    extern __shared__ char smraw[];
    float4* pbox = (float4*)smraw;                               // PFN (16-aligned)
    u64* bk      = (u64*)(smraw + (size_t)PFN*16);               // CAP keys (also final fkey)
    u16* sc      = (u16*)(smraw + (size_t)PFN*16 + (size_t)CAP*8); // NA surrogate u16

    __shared__ float4 kbox[KMAX];
    __shared__ float kar[KMAX], kscv[KMAX];
    __shared__ unsigned hist[256];
    __shared__ float4 cbox[32];
    __shared__ float car[32], cs[32];
    __shared__ unsigned conf[32];
    __shared__ int sup[32];
    __shared__ unsigned s_vmask, s_pref;
    __shared__ int s_total, s_selbin, s_cumlo, s_cumhi, s_sub, s_subPe, s_subPi;
    __shared__ int s_cnt, s_kept, s_rank, s_last, s_kkv, s_Tv;

    int tid = threadIdx.x;
    int lane = tid & 31, w = tid >> 5;
    int bc = blockIdx.x;
    int b = bc / NC, c = bc % NC;

    const float* c0 = cls0 + ((size_t)b*NC + c)*NA0;
    const float* c1 = cls1 + ((size_t)b*NC + c)*NA1;
    const float* c2 = cls2 + ((size_t)b*NC + c)*NA2;
    const float* o0 = obj0 + (size_t)b*NA0;
    const float* o1 = obj1 + (size_t)b*NA1;
    const float* o2 = obj2 + (size_t)b*NA2;

    // ---- phase 1: surrogate u16 + fused histogram (bins = v>>8) ----
    hist[tid] = 0;
    if (tid == 0){ s_kept = 0; s_rank = 0; }
    __syncthreads();
    {
        const float4* cv0 = (const float4*)c0;
        const float4* cv1 = (const float4*)c1;
        const float4* cv2 = (const float4*)c2;
        const float4* qv  = (const float4*)(g_qo + (size_t)b*NA);
        ushort4* scv = (ushort4*)sc;
        const int NQ = (2100 + NTH - 1)/NTH;    // 9
        for (int it = 0; it < NQ; it++){
            int i = it*NTH + tid;
            if (i < 2100){
                float4 cv;
                if (i < 1600) cv = cv0[i];
                else if (i < 2000) cv = cv1[i-1600];
                else cv = cv2[i-2000];
                float4 q = qv[i];
                ushort4 o;
                o.x = q2u16(qapprox(cv.x)*q.x);
                o.y = q2u16(qapprox(cv.y)*q.y);
                o.z = q2u16(qapprox(cv.z)*q.z);
                o.w = q2u16(qapprox(cv.w)*q.w);
                scv[i] = o;
                if (o.x < VHI) atomicAdd(&hist[o.x>>8], 1u);
                if (o.y < VHI) atomicAdd(&hist[o.y>>8], 1u);
                if (o.z < VHI) atomicAdd(&hist[o.z>>8], 1u);
                if (o.w < VHI) atomicAdd(&hist[o.w>>8], 1u);
            }
        }
    }
    __syncthreads();

    int prevT = -1;           // last accepted v (exclusive lower bound for next batch)
    bool haveHist = true, done = false;
    const uint2* sc4 = (const uint2*)sc;     // 4 u16 per uint2
    const int NQ4 = (2100 + NTH - 1)/NTH;    // 9

    while (!done){
        if (!haveHist){
            hist[tid] = 0; __syncthreads();
            for (int it = 0; it < NQ4; it++){
                int i = it*NTH + tid;
                if (i < 2100){
                    uint2 pv = sc4[i];
                    unsigned v0 = pv.x & 0xFFFFu, v1 = pv.x >> 16;
                    unsigned v2 = pv.y & 0xFFFFu, v3 = pv.y >> 16;
                    if (v0 < VHI && (int)v0 > prevT) atomicAdd(&hist[v0>>8], 1u);
                    if (v1 < VHI && (int)v1 > prevT) atomicAdd(&hist[v1>>8], 1u);
                    if (v2 < VHI && (int)v2 > prevT) atomicAdd(&hist[v2>>8], 1u);
                    if (v3 < VHI && (int)v3 > prevT) atomicAdd(&hist[v3>>8], 1u);
                }
            }
            __syncthreads();
        }
        // ---- select threshold bin (warp 0) ----
        if (tid < 32){
            unsigned cc[8]; unsigned sum = 0;
            #pragma unroll
            for (int j = 0; j < 8; j++){ cc[j] = hist[lane*8+j]; sum += cc[j]; }
            unsigned incl = sum;
            #pragma unroll
            for (int off = 1; off < 32; off <<= 1){
                unsigned n = __shfl_up_sync(FULLM, incl, off);
                if (lane >= off) incl += n;
            }
            unsigned excl = incl - sum;
            unsigned total = __shfl_sync(FULLM, incl, 31);
            if (lane == 0) s_total = (int)total;
            if (total > CAP && (int)excl < TSEL && TSEL <= (int)incl){
                unsigned run = excl;
                #pragma unroll
                for (int j = 0; j < 8; j++){
                    if ((int)(run + cc[j]) >= TSEL){
                        s_selbin = lane*8+j; s_cumlo = (int)run; s_cumhi = (int)(run+cc[j]);
                        break;
                    }
                    run += cc[j];
                }
            }
        }
        __syncthreads();
        int total = s_total;
        if (total == 0) break;
        bool takeall = (total <= CAP);

        if (takeall){
            if (tid == 0) s_Tv = (int)VHI - 1;
        } else if (s_cumhi <= CAP){
            if (tid == 0) s_Tv = ((s_selbin+1)<<8) - 1;
        } else {
            // refine within straddling bin on low byte (rare)
            int selbin = s_selbin;
            __syncthreads();
            hist[tid] = 0; __syncthreads();
            for (int it = 0; it < NQ4; it++){
                int i = it*NTH + tid;
                if (i < 2100){
                    uint2 pv = sc4[i];
                    unsigned vv[4] = {pv.x & 0xFFFFu, pv.x >> 16, pv.y & 0xFFFFu, pv.y >> 16};
                    #pragma unroll
                    for (int k = 0; k < 4; k++){
                        unsigned v = vv[k];
                        if (v < VHI && (int)v > prevT && (int)(v>>8) == selbin)
                            atomicAdd(&hist[v & 255u], 1u);
                    }
                }
            }
            __syncthreads();
            if (tid < 32){
                int target2 = TSEL - s_cumlo;
                unsigned cc[8]; unsigned sum = 0;
                #pragma unroll
                for (int j = 0; j < 8; j++){ cc[j] = hist[lane*8+j]; sum += cc[j]; }
                unsigned incl = sum;
                #pragma unroll
                for (int off = 1; off < 32; off <<= 1){
                    unsigned n = __shfl_up_sync(FULLM, incl, off);
                    if (lane >= off) incl += n;
                }
                unsigned excl = incl - sum;
                if ((int)excl < target2 && target2 <= (int)incl){
                    unsigned run = excl;
                    #pragma unroll
                    for (int j = 0; j < 8; j++){
                        if ((int)(run + cc[j]) >= target2){
                            s_sub = lane*8+j; s_subPe = (int)run; s_subPi = (int)(run+cc[j]);
                            break;
                        }
                        run += cc[j];
                    }
                }
            }
            __syncthreads();
            if (tid == 0){
                int sub = s_sub;
                if (s_cumlo + s_subPi > CAP && s_subPe > 0) sub -= 1;
                s_Tv = (selbin<<8) + sub;
            }
        }
        __syncthreads();
        int Tv = s_Tv;

        // ---- compact candidate indices ----
        if (tid == 0) s_cnt = 0;
        __syncthreads();
        for (int it = 0; it < NQ4; it++){
            int i = it*NTH + tid;
            if (i < 2100){
                uint2 pv = sc4[i];
                unsigned vv[4] = {pv.x & 0xFFFFu, pv.x >> 16, pv.y & 0xFFFFu, pv.y >> 16};
                #pragma unroll
                for (int k = 0; k < 4; k++){
                    int v = (int)vv[k];
                    if (v > prevT && v <= Tv){
                        int p = atomicAdd(&s_cnt, 1);
                        if (p < CAP) bk[p] = (u64)(unsigned)(4*i + k);
                    }
                }
            }
        }
        __syncthreads();
        int cnt = min(s_cnt, CAP);
        int sortN = (cnt <= 256) ? 256 : 512;

        // ---- exact rescore (bit-identical to reference path) ----
        for (int p = tid; p < sortN; p += NTH){
            if (p < cnt){
                int a = (int)(unsigned)bk[p];
                float cv = cls_at(a, c0, c1, c2);
                float ov = obj_at(a, o0, o1, o2);
                float s = (1.0f/(1.0f+expf(-cv))) * (1.0f/(1.0f+expf(-ov)));
                bk[p] = (s > SCORE_THR)
                    ? (((u64)(~__float_as_uint(s)) << 32) | (unsigned)a)
                    : PADKEY;
            } else bk[p] = PADKEY;
        }
        __syncthreads();

        // ---- bitonic sort: score desc, ties lower index first ----
        for (int ksz = 2; ksz <= sortN; ksz <<= 1){
            for (int j = ksz >> 1; j > 0; j >>= 1){
                for (int idx = tid; idx < sortN; idx += NTH){
                    int l = idx ^ j;
                    if (l > idx){
                        u64 a0 = bk[idx], a1 = bk[l];
                        bool up = ((idx & ksz) == 0);
                        if ((a0 > a1) == up){ bk[idx] = a1; bk[l] = a0; }
                    }
                }
                __syncthreads();
            }
        }

        // ---- decode boxes for first PFN sorted candidates ----
        int pn = min(cnt, PFN);
        for (int p = tid; p < pn; p += NTH){
            u64 k2 = bk[p];
            if (k2 != PADKEY)
                pbox[p] = decode_box((int)(unsigned)(k2 & 0xFFFFFFFFull), b, bb0, bb1, bb2);
        }
        __syncthreads();

        // ---- greedy NMS over chunks of 32 sorted candidates ----
        int t0 = 0;
        while (t0 < cnt){
            int K = s_kept, rank = s_rank;
            if (K >= KMAX || rank >= PRE_TOPK) break;
            int chunk_n = min(32, cnt - t0);

            if (tid < 32){
                bool lv = lane < chunk_n;
                u64 k2 = lv ? bk[t0+lane] : PADKEY;
                bool cvalid = lv && (k2 != PADKEY);
                float4 bb = make_float4(0.f,0.f,0.f,0.f);
                float sval = 0.f;
                if (cvalid){
                    int t = t0 + lane;
                    int a = (int)(unsigned)(k2 & 0xFFFFFFFFull);
                    sval = __uint_as_float(~(unsigned)(k2>>32));
                    bb = (t < pn) ? pbox[t] : decode_box(a, b, bb0, bb1, bb2);
                }
                cbox[lane] = bb;
                car[lane] = (bb.z-bb.x)*(bb.w-bb.y);
                cs[lane] = sval;
                conf[lane]=0; sup[lane]=0;
                unsigned vm = __ballot_sync(FULLM, cvalid);
                if (lane == 0) s_vmask = vm;
            }
            __syncthreads();
            unsigned vm = s_vmask;

            {   // all 8 warps: kept-suppression + intra-chunk conflict matrix
                int i = lane;
                if ((vm>>i)&1u){
                    float4 B = cbox[i]; float barV = car[i];
                    bool s = false;
                    for (int m = w; m < K; m += 8)
                        s |= iou_sup(kbox[m], kar[m], B, barV);
                    if (s) sup[i] = 1;
                    unsigned cf = 0;
                    for (int j = w; j < i; j += 8){
                        if ((vm>>j)&1u){
                            if (iou_sup(cbox[j], car[j], B, barV)) cf |= 1u<<j;
                        }
                    }
                    if (cf) atomicOr(&conf[i], cf);
                }
            }
            __syncthreads();

            if (tid < 32){
                bool base_ok = ((vm>>lane)&1u) && (sup[lane] == 0);
                unsigned myconf = conf[lane];
                unsigned undecided = __ballot_sync(FULLM, base_ok);
                unsigned kept_mask = 0;
                while (undecided){
                    bool und = (undecided >> lane) & 1u;
                    bool decidable = und && ((myconf & undecided & ~(1u<<lane)) == 0);
                    bool keepme = decidable && ((myconf & kept_mask) == 0);
                    unsigned dec = __ballot_sync(FULLM, decidable);
                    unsigned kp  = __ballot_sync(FULLM, keepme);
                    kept_mask |= kp;
                    undecided &= ~dec;
                }
                int pos = K + __popc(kept_mask & ((1u<<lane)-1u));
                if (((kept_mask>>lane)&1u) && pos < KMAX){
                    kbox[pos] = cbox[lane];
                    kar[pos] = car[lane]; kscv[pos] = cs[lane];
                }
                if (lane == 0){
                    s_kept = min(K + __popc(kept_mask), KMAX);
                    s_rank = rank + __popc(vm);
                }
            }
            __syncthreads();
            t0 += 32;
        }

        if (s_kept >= KMAX || s_rank >= PRE_TOPK || takeall) done = true;
        else { prevT = Tv; haveHist = false; }
        __syncthreads();
    }

    // ---- per-class outputs ----
    int kept = s_kept;
    float* keptS = g_kept_score + (size_t)bc*KMAX;
    float* keptB = g_kept_box   + (size_t)bc*KMAX*4;
    for (int j = tid; j < KMAX; j += NTH){
        if (j < kept){
            keptS[j] = kscv[j];
            float4 kb = kbox[j];
            keptB[j*4+0]=kb.x; keptB[j*4+1]=kb.y; keptB[j*4+2]=kb.z; keptB[j*4+3]=kb.w;
        } else {
            keptS[j] = -1.f;
            keptB[j*4+0]=0.f; keptB[j*4+1]=0.f; keptB[j*4+2]=0.f; keptB[j*4+3]=0.f;
        }
    }

    // ---- last CTA of this image runs the global top-100 ----
    __threadfence();
    __syncthreads();
    if (tid == 0){
        int r = atomicAdd(&g_done[b], 1);
        s_last = (r == NC - 1) ? 1 : 0;
    }
    __syncthreads();
    if (!s_last) return;
    __threadfence();

    u64* fkey = bk;   // alias: batch buffer free now
    const float* ks = g_kept_score + (size_t)b*TOTK;
    const int NJ = (TOTK + NTH - 1)/NTH;

    unsigned prefix = 0; int kk = KMAX;
    for (int shift = 24; shift >= 0; shift -= 8){
        unsigned mask = (shift == 24) ? 0u : (0xFFFFFFFFu << (shift+8));
        hist[tid] = 0; __syncthreads();
        for (int it = 0; it < NJ; it++){
            int j = it*NTH + tid;
            if (j < TOTK){
                unsigned u = __float_as_uint(ks[j]);
                unsigned v = (u & 0x80000000u) ? ~u : (u | 0x80000000u);
                if ((v & mask) == prefix) atomicAdd(&hist[(v>>shift)&255], 1u);
            }
        }
        __syncthreads();
        if (tid < 32){
            unsigned cc[8]; unsigned sum = 0;
            #pragma unroll
            for (int q = 0; q < 8; q++){ cc[q] = hist[lane*8+q]; sum += cc[q]; }
            unsigned incl = sum;
            #pragma unroll
            for (int off = 1; off < 32; off <<= 1){
                unsigned n = __shfl_down_sync(FULLM, incl, off);
                if (lane + off < 32) incl += n;
            }
            unsigned below = incl - sum;
            if ((int)below < kk && kk <= (int)incl){
                unsigned run = below;
                for (int q = 7; q >= 0; q--){
                    if (run + cc[q] >= (unsigned)kk){
                        s_pref = prefix | (((unsigned)(lane*8+q)) << shift);
                        s_kkv  = kk - (int)run;
                        break;
                    }
                    run += cc[q];
                }
            }
        }
        __syncthreads();
        prefix = s_pref; kk = s_kkv;
        __syncthreads();
    }
    unsigned T = prefix;
    const unsigned MAP0 = 0x80000000u;

    if (tid == 0) s_cnt = 0;
    __syncthreads();
    for (int it = 0; it < NJ; it++){
        int j = it*NTH + tid;
        bool inb = j < TOTK;
        unsigned v = 0;
        if (inb){
            unsigned u = __float_as_uint(ks[j]);
            v = (u & 0x80000000u) ? ~u : (u | 0x80000000u);
        }
        wappend(fkey, &s_cnt, inb && v >= T && v > MAP0,
                ((u64)v << 32) | (0xFFFFFFFFu - (unsigned)j), FSORT);
    }
    __syncthreads();
    int fcnt = min(s_cnt, FSORT);
    for (int p = fcnt + tid; p < FSORT; p += NTH) fkey[p] = 0ull;
    __syncthreads();

    for (int ksz = 2; ksz <= FSORT; ksz <<= 1){
        for (int j = ksz >> 1; j > 0; j >>= 1){
            if (tid < FSORT){
                int idx = tid, l = idx ^ j;
                if (l > idx){
                    u64 a0 = fkey[idx], a1 = fkey[l];
                    bool up = ((idx & ksz) == 0);
                    if ((a0 > a1) == up){ fkey[idx] = a1; fkey[l] = a0; }
                }
            }
            __syncthreads();
        }
    }

    float* out_num = out;
    float* out_box = out + BATCH;
    float* out_sc  = out + BATCH + (size_t)BATCH*KMAX*4;
    float* out_cl  = out + BATCH + (size_t)BATCH*KMAX*4 + (size_t)BATCH*KMAX;

    for (int k = tid; k < KMAX; k += NTH){
        bool valid = (k < fcnt);
        float s = 0.f, cl = -1.f, b0=0.f, b1=0.f, b2=0.f, b3=0.f;
        if (valid){
            u64 k2 = fkey[FSORT-1-k];
            int flat = (int)(0xFFFFFFFFu - (unsigned)(k2 & 0xFFFFFFFFull));
            s  = g_kept_score[(size_t)b*TOTK + flat];
            cl = (float)(flat / KMAX);
            const float* bb = &g_kept_box[((size_t)b*TOTK + flat)*4];
            b0 = bb[0]; b1 = bb[1]; b2 = bb[2]; b3 = bb[3];
        }
        out_sc[(size_t)b*KMAX + k] = s;
        out_cl[(size_t)b*KMAX + k] = cl;
        float* ob = &out_box[((size_t)b*KMAX + k)*4];
        ob[0]=b0; ob[1]=b1; ob[2]=b2; ob[3]=b3;
    }
    if (tid == 0){
        out_num[b] = (float)min(fcnt, KMAX);
        g_done[b] = 0;              // reset for next graph replay
    }
}

// ---------------- launch ----------------
extern "C" void kernel_launch(void* const* d_in, const int* in_sizes, int n_in,
                              void* d_out, int out_size){
    const float* cls0 = (const float*)d_in[0];
    const float* bb0  = (const float*)d_in[1];
    const float* obj0 = (const float*)d_in[2];
    const float* cls1 = (const float*)d_in[3];
    const float* bb1  = (const float*)d_in[4];
    const float* obj1 = (const float*)d_in[5];
    const float* cls2 = (const float*)d_in[6];
    const float* bb2  = (const float*)d_in[7];
    const float* obj2 = (const float*)d_in[8];
    float* out = (float*)d_out;

    int n = BATCH*NA;
    k_obj<<<(n+255)/256, 256>>>(obj0, obj1, obj2);

    size_t smem = (size_t)PFN*16 + (size_t)CAP*8 + (size_t)NA*2;  // 22,944 B
    k_all<<<BATCH*NC, NTH, smem>>>(cls0, bb0, obj0, cls1, bb1, obj1,
                                   cls2, bb2, obj2, out);
}

// round 11
// speedup vs baseline: 1.4796x; 1.4796x over previous
#include <cuda_runtime.h>
#include <math.h>

#define BATCH 8
#define NC 80
#define NA 8400
#define NA0 6400
#define NA1 1600
#define NA2 400
#define PRE_TOPK 5000
#define KMAX 100
#define TOTK (NC*KMAX)
#define SCORE_THR 0.01f
#define IOU_THR 0.65f
#define NTH 256
#define CAP 512
#define TSEL 128
#define ACC 288
#define FSORT 256
#define PFN 128
#define PADKEY 0xFFFFFFFFFFFFFFFFull
#define FULLM 0xFFFFFFFFu
#define QBASE 0x3F800000u
typedef unsigned long long u64;

// ---------------- scratch ----------------
__device__ float g_kept_score[BATCH*TOTK];
__device__ float g_kept_box  [BATCH*TOTK*4];
__device__ int   g_done[BATCH];          // zero-init; self-resetting per replay

// decision-exact IoU>thr; IEEE div only in tiny ambiguity band
__device__ __forceinline__ bool iou_sup(float4 A, float aar, float4 B, float bar){
    float tlx = fmaxf(A.x, B.x), tly = fmaxf(A.y, B.y);
    float brx = fminf(A.z, B.z), bry = fminf(A.w, B.w);
    float ww = fmaxf(brx - tlx, 0.f), hh = fmaxf(bry - tly, 0.f);
    float inter = ww*hh;
    float denom = aar + bar - inter + 1e-6f;
    float d = inter - IOU_THR*denom;
    if (fabsf(d) > 1e-4f*denom) return d > 0.f;
    return __fdiv_rn(inter, denom) > IOU_THR;
}

// monotone cheap approx of 1+e^{-x} (selection surrogate only)
__device__ __forceinline__ float qapprox(float x){
    float t = fminf(fmaxf(-x, -80.f), 80.f);
    int bits = (int)(12102203.0f*t + 1064986316.0f);
    return 1.0f + __int_as_float(bits);
}

// warp-aggregated append (final phase)
__device__ __forceinline__ void wappend(u64* buf, int* cnt, bool pred, u64 val, int bound){
    unsigned pm = __ballot_sync(FULLM, pred);
    if (!pm) return;
    int lane = (int)(threadIdx.x & 31);
    int ldr  = __ffs(pm) - 1;
    int base = 0;
    if (lane == ldr) base = atomicAdd(cnt, __popc(pm));
    base = __shfl_sync(FULLM, base, ldr);
    if (pred){
        int p = base + __popc(pm & ((1u<<lane)-1u));
        if (p < bound) buf[p] = val;
    }
}

// exact box decode (identical arithmetic to all passing rounds)
__device__ __forceinline__ float4 decode_box(int a, int b,
        const float* __restrict__ bb0, const float* __restrict__ bb1,
        const float* __restrict__ bb2){
    float p0,p1,p2,p3,px,py,st;
    if (a < NA0){ int hw=a; const float* p=bb0+(size_t)b*4*NA0;
        p0=p[hw];p1=p[NA0+hw];p2=p[2*NA0+hw];p3=p[3*NA0+hw];
        px=(float)(hw%80)*8.f; py=(float)(hw/80)*8.f; st=8.f;
    } else if (a < NA0+NA1){ int hw=a-NA0; const float* p=bb1+(size_t)b*4*NA1;
        p0=p[hw];p1=p[NA1+hw];p2=p[2*NA1+hw];p3=p[3*NA1+hw];
        px=(float)(hw%40)*16.f; py=(float)(hw/40)*16.f; st=16.f;
    } else { int hw=a-NA0-NA1; const float* p=bb2+(size_t)b*4*NA2;
        p0=p[hw];p1=p[NA2+hw];p2=p[2*NA2+hw];p3=p[3*NA2+hw];
        px=(float)(hw%20)*32.f; py=(float)(hw/20)*32.f; st=32.f;
    }
    float cx=p0*st+px, cy=p1*st+py, w=expf(p2)*st, h=expf(p3)*st;
    return make_float4(cx-w*0.5f, cy-h*0.5f, cx+w*0.5f, cy+h*0.5f);
}

__device__ __forceinline__ float cls_at(int a, const float* c0, const float* c1, const float* c2){
    if (a < NA0) return c0[a];
    if (a < NA0+NA1) return c1[a-NA0];
    return c2[a-NA0-NA1];
}
__device__ __forceinline__ float obj_at(int a, const float* o0, const float* o1, const float* o2){
    if (a < NA0) return o0[a];
    if (a < NA0+NA1) return o1[a-NA0];
    return o2[a-NA0-NA1];
}

// ---------------- the fused kernel ----------------
__global__ __launch_bounds__(NTH, 5) void k_all(
    const float* __restrict__ cls0, const float* __restrict__ bb0, const float* __restrict__ obj0,
    const float* __restrict__ cls1, const float* __restrict__ bb1, const float* __restrict__ obj1,
    const float* __restrict__ cls2, const float* __restrict__ bb2, const float* __restrict__ obj2,
    float* __restrict__ out){

    extern __shared__ char smraw[];
    unsigned* sc = (unsigned*)smraw;                             // NA surrogate q-bits
    u64* bk      = (u64*)(smraw + (size_t)NA*4);                 // CAP keys (also final fkey)
    float4* pbox = (float4*)(smraw + (size_t)NA*4 + (size_t)CAP*8); // PFN decoded boxes

    __shared__ float4 kbox[KMAX];
    __shared__ float kar[KMAX], kscv[KMAX];
    __shared__ unsigned hist[256];
    __shared__ float4 cbox[32];
    __shared__ float car[32], cs[32];
    __shared__ unsigned conf[32];
    __shared__ int sup[32];
    __shared__ unsigned s_Tbits, s_vmask, s_pref;
    __shared__ int s_total, s_selbin, s_cumlo, s_cumhi, s_sub, s_subPe, s_subPi;
    __shared__ int s_cnt, s_kept, s_rank, s_last, s_kkv;

    int tid = threadIdx.x;
    int lane = tid & 31, w = tid >> 5;
    int bc = blockIdx.x;
    int b = bc / NC, c = bc % NC;

    const float* c0 = cls0 + ((size_t)b*NC + c)*NA0;
    const float* c1 = cls1 + ((size_t)b*NC + c)*NA1;
    const float* c2 = cls2 + ((size_t)b*NC + c)*NA2;
    const float* o0 = obj0 + (size_t)b*NA0;
    const float* o1 = obj1 + (size_t)b*NA1;
    const float* o2 = obj2 + (size_t)b*NA2;

    const unsigned QHI = __float_as_uint(110.0f);   // surrogate ~score>0.009 band

    // ---- phase 1: compute surrogate q-bits, store to smem, fused 214-bin histogram
    hist[tid] = 0;
    if (tid == 0){ s_kept = 0; s_rank = 0; }
    __syncthreads();
    {
        const float4* c0v = (const float4*)c0;
        const float4* c1v = (const float4*)c1;
        const float4* c2v = (const float4*)c2;
        const float4* o0v = (const float4*)o0;
        const float4* o1v = (const float4*)o1;
        const float4* o2v = (const float4*)o2;
        uint4* scv = (uint4*)sc;
        const int NQ = (2100 + NTH - 1)/NTH;    // 9
        for (int it = 0; it < NQ; it++){
            int i = it*NTH + tid;
            if (i < 2100){
                float4 cv, ov;
                if (i < 1600){ cv = c0v[i]; ov = o0v[i]; }
                else if (i < 2000){ cv = c1v[i-1600]; ov = o1v[i-1600]; }
                else { cv = c2v[i-2000]; ov = o2v[i-2000]; }
                uint4 o;
                o.x = __float_as_uint(qapprox(cv.x)*qapprox(ov.x));
                o.y = __float_as_uint(qapprox(cv.y)*qapprox(ov.y));
                o.z = __float_as_uint(qapprox(cv.z)*qapprox(ov.z));
                o.w = __float_as_uint(qapprox(cv.w)*qapprox(ov.w));
                scv[i] = o;
                if (o.x < QHI) atomicAdd(&hist[(o.x-QBASE)>>18], 1u);
                if (o.y < QHI) atomicAdd(&hist[(o.y-QBASE)>>18], 1u);
                if (o.z < QHI) atomicAdd(&hist[(o.z-QBASE)>>18], 1u);
                if (o.w < QHI) atomicAdd(&hist[(o.w-QBASE)>>18], 1u);
            }
        }
    }
    __syncthreads();

    unsigned prevT = 0;
    bool haveHist = true, done = false;
    const uint2* sc2 = (const uint2*)sc;
    const int NH2 = (NA/2 + NTH - 1)/NTH;   // 17

    while (!done){
        if (!haveHist){
            hist[tid] = 0; __syncthreads();
            for (int it = 0; it < NH2; it++){
                int i = it*NTH + tid;
                if (i < NA/2){
                    uint2 v = sc2[i];
                    if (v.x < QHI && v.x > prevT) atomicAdd(&hist[(v.x-QBASE)>>18], 1u);
                    if (v.y < QHI && v.y > prevT) atomicAdd(&hist[(v.y-QBASE)>>18], 1u);
                }
            }
            __syncthreads();
        }
        // ---- select threshold bin (warp 0) ----
        if (tid < 32){
            unsigned cc[8]; unsigned sum = 0;
            #pragma unroll
            for (int j = 0; j < 8; j++){ cc[j] = hist[lane*8+j]; sum += cc[j]; }
            unsigned incl = sum;
            #pragma unroll
            for (int off = 1; off < 32; off <<= 1){
                unsigned n = __shfl_up_sync(FULLM, incl, off);
                if (lane >= off) incl += n;
            }
            unsigned excl = incl - sum;
            unsigned total = __shfl_sync(FULLM, incl, 31);
            if (lane == 0) s_total = (int)total;
            if (total > CAP && (int)excl < TSEL && TSEL <= (int)incl){
                unsigned run = excl;
                #pragma unroll
                for (int j = 0; j < 8; j++){
                    if ((int)(run + cc[j]) >= TSEL){
                        s_selbin = lane*8+j; s_cumlo = (int)run; s_cumhi = (int)(run+cc[j]);
                        break;
                    }
                    run += cc[j];
                }
            }
        }
        __syncthreads();
        int total = s_total;
        if (total == 0) break;
        bool takeall = (total <= CAP);

        if (takeall){
            if (tid == 0) s_Tbits = QHI - 1u;
        } else if (s_cumhi <= ACC){
            if (tid == 0) s_Tbits = QBASE + (((unsigned)s_selbin+1u)<<18) - 1u;
        } else {
            // refine within straddling bin on bits>>10
            int selbin = s_selbin;
            __syncthreads();
            hist[tid] = 0; __syncthreads();
            for (int it = 0; it < NH2; it++){
                int i = it*NTH + tid;
                if (i < NA/2){
                    uint2 v = sc2[i];
                    if (v.x < QHI && v.x > prevT && (int)((v.x-QBASE)>>18) == selbin)
                        atomicAdd(&hist[(v.x>>10)&255], 1u);
                    if (v.y < QHI && v.y > prevT && (int)((v.y-QBASE)>>18) == selbin)
                        atomicAdd(&hist[(v.y>>10)&255], 1u);
                }
            }
            __syncthreads();
            if (tid < 32){
                int target2 = TSEL - s_cumlo;
                if (target2 < 1) target2 = 1;
                unsigned cc[8]; unsigned sum = 0;
                #pragma unroll
                for (int j = 0; j < 8; j++){ cc[j] = hist[lane*8+j]; sum += cc[j]; }
                unsigned incl = sum;
                #pragma unroll
                for (int off = 1; off < 32; off <<= 1){
                    unsigned n = __shfl_up_sync(FULLM, incl, off);
                    if (lane >= off) incl += n;
                }
                unsigned excl = incl - sum;
                if ((int)excl < target2 && target2 <= (int)incl){
                    unsigned run = excl;
                    #pragma unroll
                    for (int j = 0; j < 8; j++){
                        if ((int)(run + cc[j]) >= target2){
                            s_sub = lane*8+j; s_subPe = (int)run; s_subPi = (int)(run+cc[j]);
                            break;
                        }
                        run += cc[j];
                    }
                }
            }
            __syncthreads();
            if (tid == 0){
                int sub = s_sub;
                if (s_cumlo + s_subPi > CAP && s_subPe > 0) sub -= 1;
                s_Tbits = QBASE + (((unsigned)selbin)<<18) + (((unsigned)sub+1u)<<10) - 1u;
            }
        }
        __syncthreads();
        unsigned Tbits = s_Tbits;

        // ---- compact candidate indices ----
        if (tid == 0) s_cnt = 0;
        __syncthreads();
        for (int it = 0; it < NH2; it++){
            int i = it*NTH + tid;
            if (i < NA/2){
                uint2 v = sc2[i];
                if (v.x > prevT && v.x <= Tbits){
                    int p = atomicAdd(&s_cnt, 1);
                    if (p < CAP) bk[p] = (u64)(unsigned)(2*i);
                }
                if (v.y > prevT && v.y <= Tbits){
                    int p = atomicAdd(&s_cnt, 1);
                    if (p < CAP) bk[p] = (u64)(unsigned)(2*i+1);
                }
            }
        }
        __syncthreads();
        int cnt = min(s_cnt, CAP);
        int sortN = (cnt <= 128) ? 128 : ((cnt <= 256) ? 256 : 512);

        // ---- exact rescore (bit-identical to reference path) ----
        for (int p = tid; p < sortN; p += NTH){
            if (p < cnt){
                int a = (int)(unsigned)bk[p];
                float cv = cls_at(a, c0, c1, c2);
                float ov = obj_at(a, o0, o1, o2);
                float s = (1.0f/(1.0f+expf(-cv))) * (1.0f/(1.0f+expf(-ov)));
                bk[p] = (s > SCORE_THR)
                    ? (((u64)(~__float_as_uint(s)) << 32) | (unsigned)a)
                    : PADKEY;
            } else bk[p] = PADKEY;
        }
        __syncthreads();

        // ---- bitonic sort: score desc, ties lower index first ----
        for (int ksz = 2; ksz <= sortN; ksz <<= 1){
            for (int j = ksz >> 1; j > 0; j >>= 1){
                for (int idx = tid; idx < sortN; idx += NTH){
                    int l = idx ^ j;
                    if (l > idx){
                        u64 a0 = bk[idx], a1 = bk[l];
                        bool up = ((idx & ksz) == 0);
                        if ((a0 > a1) == up){ bk[idx] = a1; bk[l] = a0; }
                    }
                }
                __syncthreads();
            }
        }

        // ---- decode boxes for first PFN sorted candidates ----
        int pn = min(cnt, PFN);
        for (int p = tid; p < pn; p += NTH){
            u64 k2 = bk[p];
            if (k2 != PADKEY)
                pbox[p] = decode_box((int)(unsigned)(k2 & 0xFFFFFFFFull), b, bb0, bb1, bb2);
        }
        __syncthreads();

        // ---- greedy NMS over chunks of 32 sorted candidates ----
        int t0 = 0;
        while (t0 < cnt){
            int K = s_kept, rank = s_rank;
            if (K >= KMAX || rank >= PRE_TOPK) break;
            int chunk_n = min(32, cnt - t0);

            if (tid < 32){
                bool lv = lane < chunk_n;
                u64 k2 = lv ? bk[t0+lane] : PADKEY;
                bool cvalid = lv && (k2 != PADKEY);
                float4 bb = make_float4(0.f,0.f,0.f,0.f);
                float sval = 0.f;
                if (cvalid){
                    int t = t0 + lane;
                    int a = (int)(unsigned)(k2 & 0xFFFFFFFFull);
                    sval = __uint_as_float(~(unsigned)(k2>>32));
                    bb = (t < pn) ? pbox[t] : decode_box(a, b, bb0, bb1, bb2);
                }
                cbox[lane] = bb;
                car[lane] = (bb.z-bb.x)*(bb.w-bb.y);
                cs[lane] = sval;
                conf[lane]=0; sup[lane]=0;
                unsigned vm = __ballot_sync(FULLM, cvalid);
                if (lane == 0) s_vmask = vm;
            }
            __syncthreads();
            unsigned vm = s_vmask;

            {   // all 8 warps: kept-suppression + intra-chunk conflict matrix
                int i = lane;
                if ((vm>>i)&1u){
                    float4 B = cbox[i]; float barV = car[i];
                    bool s = false;
                    for (int m = w; m < K; m += 8)
                        s |= iou_sup(kbox[m], kar[m], B, barV);
                    if (s) sup[i] = 1;
                    unsigned cf = 0;
                    for (int j = w; j < i; j += 8){
                        if ((vm>>j)&1u){
                            if (iou_sup(cbox[j], car[j], B, barV)) cf |= 1u<<j;
                        }
                    }
                    if (cf) atomicOr(&conf[i], cf);
                }
            }
            __syncthreads();

            if (tid < 32){
                bool base_ok = ((vm>>lane)&1u) && (sup[lane] == 0);
                unsigned myconf = conf[lane];
                unsigned undecided = __ballot_sync(FULLM, base_ok);
                unsigned kept_mask = 0;
                while (undecided){
                    bool und = (undecided >> lane) & 1u;
                    bool decidable = und && ((myconf & undecided & ~(1u<<lane)) == 0);
                    bool keepme = decidable && ((myconf & kept_mask) == 0);
                    unsigned dec = __ballot_sync(FULLM, decidable);
                    unsigned kp  = __ballot_sync(FULLM, keepme);
                    kept_mask |= kp;
                    undecided &= ~dec;
                }
                int pos = K + __popc(kept_mask & ((1u<<lane)-1u));
                if (((kept_mask>>lane)&1u) && pos < KMAX){
                    kbox[pos] = cbox[lane];
                    kar[pos] = car[lane]; kscv[pos] = cs[lane];
                }
                if (lane == 0){
                    s_kept = min(K + __popc(kept_mask), KMAX);
                    s_rank = rank + __popc(vm);
                }
            }
            __syncthreads();
            t0 += 32;
        }

        if (s_kept >= KMAX || s_rank >= PRE_TOPK || takeall) done = true;
        else { prevT = Tbits; haveHist = false; }
        __syncthreads();
    }

    // ---- per-class outputs ----
    int kept = s_kept;
    float* keptS = g_kept_score + (size_t)bc*KMAX;
    float* keptB = g_kept_box   + (size_t)bc*KMAX*4;
    for (int j = tid; j < KMAX; j += NTH){
        if (j < kept){
            keptS[j] = kscv[j];
            float4 kb = kbox[j];
            keptB[j*4+0]=kb.x; keptB[j*4+1]=kb.y; keptB[j*4+2]=kb.z; keptB[j*4+3]=kb.w;
        } else {
            keptS[j] = -1.f;
            keptB[j*4+0]=0.f; keptB[j*4+1]=0.f; keptB[j*4+2]=0.f; keptB[j*4+3]=0.f;
        }
    }

    // ---- last CTA of this image runs the global top-100 ----
    __threadfence();
    __syncthreads();
    if (tid == 0){
        int r = atomicAdd(&g_done[b], 1);
        s_last = (r == NC - 1) ? 1 : 0;
    }
    __syncthreads();
    if (!s_last) return;
    __threadfence();

    u64* fkey = bk;   // alias: batch buffer free now
    const float* ks = g_kept_score + (size_t)b*TOTK;
    const int NJ = (TOTK + NTH - 1)/NTH;

    unsigned prefix = 0; int kk = KMAX;
    for (int shift = 24; shift >= 0; shift -= 8){
        unsigned mask = (shift == 24) ? 0u : (0xFFFFFFFFu << (shift+8));
        hist[tid] = 0; __syncthreads();
        for (int it = 0; it < NJ; it++){
            int j = it*NTH + tid;
            if (j < TOTK){
                unsigned u = __float_as_uint(ks[j]);
                unsigned v = (u & 0x80000000u) ? ~u : (u | 0x80000000u);
                if ((v & mask) == prefix) atomicAdd(&hist[(v>>shift)&255], 1u);
            }
        }
        __syncthreads();
        if (tid < 32){
            unsigned cc[8]; unsigned sum = 0;
            #pragma unroll
            for (int q = 0; q < 8; q++){ cc[q] = hist[lane*8+q]; sum += cc[q]; }
            unsigned incl = sum;
            #pragma unroll
            for (int off = 1; off < 32; off <<= 1){
                unsigned n = __shfl_down_sync(FULLM, incl, off);
                if (lane + off < 32) incl += n;
            }
            unsigned below = incl - sum;
            if ((int)below < kk && kk <= (int)incl){
                unsigned run = below;
                for (int q = 7; q >= 0; q--){
                    if (run + cc[q] >= (unsigned)kk){
                        s_pref = prefix | (((unsigned)(lane*8+q)) << shift);
                        s_kkv  = kk - (int)run;
                        break;
                    }
                    run += cc[q];
                }
            }
        }
        __syncthreads();
        prefix = s_pref; kk = s_kkv;
        __syncthreads();
    }
    unsigned T = prefix;
    const unsigned MAP0 = 0x80000000u;

    if (tid == 0) s_cnt = 0;
    __syncthreads();
    for (int it = 0; it < NJ; it++){
        int j = it*NTH + tid;
        bool inb = j < TOTK;
        unsigned v = 0;
        if (inb){
            unsigned u = __float_as_uint(ks[j]);
            v = (u & 0x80000000u) ? ~u : (u | 0x80000000u);
        }
        wappend(fkey, &s_cnt, inb && v >= T && v > MAP0,
                ((u64)v << 32) | (0xFFFFFFFFu - (unsigned)j), FSORT);
    }
    __syncthreads();
    int fcnt = min(s_cnt, FSORT);
    for (int p = fcnt + tid; p < FSORT; p += NTH) fkey[p] = 0ull;
    __syncthreads();

    for (int ksz = 2; ksz <= FSORT; ksz <<= 1){
        for (int j = ksz >> 1; j > 0; j >>= 1){
            if (tid < FSORT){
                int idx = tid, l = idx ^ j;
                if (l > idx){
                    u64 a0 = fkey[idx], a1 = fkey[l];
                    bool up = ((idx & ksz) == 0);
                    if ((a0 > a1) == up){ fkey[idx] = a1; fkey[l] = a0; }
                }
            }
            __syncthreads();
        }
    }

    float* out_num = out;
    float* out_box = out + BATCH;
    float* out_sc  = out + BATCH + (size_t)BATCH*KMAX*4;
    float* out_cl  = out + BATCH + (size_t)BATCH*KMAX*4 + (size_t)BATCH*KMAX;

    for (int k = tid; k < KMAX; k += NTH){
        bool valid = (k < fcnt);
        float s = 0.f, cl = -1.f, b0=0.f, b1=0.f, b2=0.f, b3=0.f;
        if (valid){
            u64 k2 = fkey[FSORT-1-k];
            int flat = (int)(0xFFFFFFFFu - (unsigned)(k2 & 0xFFFFFFFFull));
            s  = g_kept_score[(size_t)b*TOTK + flat];
            cl = (float)(flat / KMAX);
            const float* bb = &g_kept_box[((size_t)b*TOTK + flat)*4];
            b0 = bb[0]; b1 = bb[1]; b2 = bb[2]; b3 = bb[3];
        }
        out_sc[(size_t)b*KMAX + k] = s;
        out_cl[(size_t)b*KMAX + k] = cl;
        float* ob = &out_box[((size_t)b*KMAX + k)*4];
        ob[0]=b0; ob[1]=b1; ob[2]=b2; ob[3]=b3;
    }
    if (tid == 0){
        out_num[b] = (float)min(fcnt, KMAX);
        g_done[b] = 0;              // reset for next graph replay
    }
}

// ---------------- launch ----------------
extern "C" void kernel_launch(void* const* d_in, const int* in_sizes, int n_in,
                              void* d_out, int out_size){
    const float* cls0 = (const float*)d_in[0];
    const float* bb0  = (const float*)d_in[1];
    const float* obj0 = (const float*)d_in[2];
    const float* cls1 = (const float*)d_in[3];
    const float* bb1  = (const float*)d_in[4];
    const float* obj1 = (const float*)d_in[5];
    const float* cls2 = (const float*)d_in[6];
    const float* bb2  = (const float*)d_in[7];
    const float* obj2 = (const float*)d_in[8];
    float* out = (float*)d_out;

    size_t smem = (size_t)NA*4 + (size_t)CAP*8 + (size_t)PFN*16;  // 39,744 B
    k_all<<<BATCH*NC, NTH, smem>>>(cls0, bb0, obj0, cls1, bb1, obj1,
                                   cls2, bb2, obj2, out);
}